// round 3
// baseline (speedup 1.0000x reference)
#include <cuda_runtime.h>
#include <cstdint>

// Scratch (allocation-free rule: device globals)
__device__ float g_x[4194304];  // attention output, [B*N, D]
__device__ float g_h[4194304];  // MLP hidden,      [B*N, D]

#define QPAD 34   // float2 row stride for Qp/Ep/Kp/Ap (even -> float4-aligned rows)
#define VPAD 66   // float2 row stride for Vp
#define WPAD 130  // float2 row stride for Wp

__device__ __forceinline__ float f2tf(float x) {
    uint32_t u;
    asm("cvt.rna.tf32.f32 %0, %1;" : "=r"(u) : "f"(x));
    return __uint_as_float(u);
}
__device__ __forceinline__ uint32_t fu(float x) { return __float_as_uint(x); }

// D += A @ B  (m16n8k8, tf32 in, fp32 accumulate)
__device__ __forceinline__ void mma8(float* c, const uint32_t* a, const uint32_t* b) {
    asm volatile("mma.sync.aligned.m16n8k8.row.col.f32.tf32.tf32.f32 "
        "{%0,%1,%2,%3}, {%4,%5,%6,%7}, {%8,%9}, {%0,%1,%2,%3};"
        : "+f"(c[0]), "+f"(c[1]), "+f"(c[2]), "+f"(c[3])
        : "r"(a[0]), "r"(a[1]), "r"(a[2]), "r"(a[3]), "r"(b[0]), "r"(b[1]));
}

// Pack two float4 (k..k+3 and k+4..k+7) as 4 (x[k],x[k+4]) float2 pairs, tf32-rounded.
__device__ __forceinline__ void pack_pairs(float2* d, float4 a, float4 b) {
    *(float4*)(d)     = make_float4(f2tf(a.x), f2tf(b.x), f2tf(a.y), f2tf(b.y));
    *(float4*)(d + 2) = make_float4(f2tf(a.z), f2tf(b.z), f2tf(a.w), f2tf(b.w));
}

// ---------------------------------------------------------------------------
// Fused attention: ctx = softmax(Q K^T * scale) @ V  +  pe @ V   (tf32 MMA)
// CTA = (b, h, 64-row q-tile), 128 threads (4 warps, 16 rows each).
// exp without max-subtraction (scores ~N(0,1): no overflow risk), running sum.
// P stays in registers: C-frag -> A-frag via intra-quad shuffles.
// ---------------------------------------------------------------------------
__global__ __launch_bounds__(128, 3)
void attn_kernel(const float* __restrict__ q, const float* __restrict__ k,
                 const float* __restrict__ v, const float* __restrict__ pe,
                 float* __restrict__ xout)
{
    extern __shared__ float2 sm2[];
    float2* Qp = sm2;                 // [64][QPAD]  pairs (Q[r][k], Q[r][k+4])
    float2* Ep = Qp + 64 * QPAD;      // [64][QPAD]  pe tile, same packing
    float2* Kp = Ep + 64 * QPAD;      // [64][QPAD]  pairs (K[n][k], K[n][k+4])
    float2* Vp = Kp + 64 * QPAD;      // [32][VPAD]  pairs (V[k][n], V[k+4][n])

    const int b = blockIdx.x, h = blockIdx.y, q0 = blockIdx.z * 64;
    const int tid = threadIdx.x, lane = tid & 31, warp = tid >> 5;
    const int quad = lane >> 2, qt = lane & 3;
    const int rl0 = warp * 16 + quad, rh0 = rl0 + 8;

    const float* qb  = q  + ((size_t)(b * 16 + h) * 1024 + q0) * 64;
    const float* kb  = k  + (size_t)(b * 16 + h) * 65536;
    const float* vb  = v  + (size_t)(b * 16 + h) * 65536;
    const float* peb = pe + ((size_t)h * 1024 + q0) * 1024;

    // Q tile (packed, resident)
    #pragma unroll
    for (int t = 0; t < 4; ++t) {
        int task = tid + t * 128;            // 512 tasks: r(64) x kg(8)
        int r = task >> 3, kg = task & 7;
        const float* s = qb + r * 64 + kg * 8;
        pack_pairs(&Qp[r * QPAD + kg * 4], *(const float4*)s, *(const float4*)(s + 4));
    }

    float os[8][4] = {};   // P @ V (unnormalized)
    float op[8][4] = {};   // pe @ V
    float rs_lo = 0.f, rs_hi = 0.f;

    const int srcA = quad * 4 + (qt >> 1);
    const int srcB = srcA + 2;
    const bool oddt = (qt & 1);
    const float c2 = 0.125f * 1.44269504088896340736f;  // scale * log2(e)

    for (int kt = 0; kt < 16; ++kt) {
        const int k0 = kt * 64;
        __syncthreads();
        // K tile
        #pragma unroll
        for (int t = 0; t < 4; ++t) {
            int task = tid + t * 128;
            int r = task >> 3, kg = task & 7;
            const float* s = kb + (size_t)(k0 + r) * 64 + kg * 8;
            pack_pairs(&Kp[r * QPAD + kg * 4], *(const float4*)s, *(const float4*)(s + 4));
        }
        // V tile (row pairs k, k+4)
        #pragma unroll
        for (int t = 0; t < 2; ++t) {
            int task = tid + t * 128;        // 256 tasks: pair(32) x colchunk(8)
            int pi = task >> 3, c = (task & 7) * 8;
            int kk = (pi >> 2) * 8 + (pi & 3);
            const float* s0 = vb + (size_t)(k0 + kk) * 64 + c;
            const float* s1 = s0 + 4 * 64;
            float4 a0 = *(const float4*)s0, a1 = *(const float4*)(s0 + 4);
            float4 b0 = *(const float4*)s1, b1 = *(const float4*)(s1 + 4);
            float2* d = &Vp[pi * VPAD + c];
            *(float4*)(d)     = make_float4(f2tf(a0.x), f2tf(b0.x), f2tf(a0.y), f2tf(b0.y));
            *(float4*)(d + 2) = make_float4(f2tf(a0.z), f2tf(b0.z), f2tf(a0.w), f2tf(b0.w));
            *(float4*)(d + 4) = make_float4(f2tf(a1.x), f2tf(b1.x), f2tf(a1.y), f2tf(b1.y));
            *(float4*)(d + 6) = make_float4(f2tf(a1.z), f2tf(b1.z), f2tf(a1.w), f2tf(b1.w));
        }
        // pe tile
        #pragma unroll
        for (int t = 0; t < 4; ++t) {
            int task = tid + t * 128;
            int r = task >> 3, kg = task & 7;
            const float* s = peb + (size_t)r * 1024 + k0 + kg * 8;
            pack_pairs(&Ep[r * QPAD + kg * 4], *(const float4*)s, *(const float4*)(s + 4));
        }
        __syncthreads();

        // ----- S = Q @ K^T (warp strip 16 x 64) -----
        float p[8][4] = {};
        #pragma unroll
        for (int kg = 0; kg < 8; ++kg) {
            float2 qa0 = Qp[rl0 * QPAD + kg * 4 + qt];
            float2 qa1 = Qp[rh0 * QPAD + kg * 4 + qt];
            uint32_t a[4] = {fu(qa0.x), fu(qa1.x), fu(qa0.y), fu(qa1.y)};
            #pragma unroll
            for (int ng = 0; ng < 8; ++ng) {
                float2 b2 = Kp[(ng * 8 + quad) * QPAD + kg * 4 + qt];
                uint32_t bb[2] = {fu(b2.x), fu(b2.y)};
                mma8(p[ng], a, bb);
            }
        }

        // ----- p = exp(S*scale), accumulate row sums -----
        float sl = 0.f, sh = 0.f;
        #pragma unroll
        for (int ng = 0; ng < 8; ++ng) {
            p[ng][0] = exp2f(p[ng][0] * c2);
            p[ng][1] = exp2f(p[ng][1] * c2);
            p[ng][2] = exp2f(p[ng][2] * c2);
            p[ng][3] = exp2f(p[ng][3] * c2);
            sl += p[ng][0] + p[ng][1];
            sh += p[ng][2] + p[ng][3];
        }
        sl += __shfl_xor_sync(0xffffffffu, sl, 1);
        sl += __shfl_xor_sync(0xffffffffu, sl, 2);
        sh += __shfl_xor_sync(0xffffffffu, sh, 1);
        sh += __shfl_xor_sync(0xffffffffu, sh, 2);
        rs_lo += sl; rs_hi += sh;

        // ----- os += P @ V ; op += E @ V  (shared V B-fragments) -----
        #pragma unroll
        for (int kg = 0; kg < 8; ++kg) {
            // C-layout (cols 2qt,2qt+1) -> A-layout (cols qt, qt+4) via quad shuffles
            float x0 = __shfl_sync(0xffffffffu, p[kg][0], srcA);
            float x1 = __shfl_sync(0xffffffffu, p[kg][1], srcA);
            float x2 = __shfl_sync(0xffffffffu, p[kg][2], srcA);
            float x3 = __shfl_sync(0xffffffffu, p[kg][3], srcA);
            float y0 = __shfl_sync(0xffffffffu, p[kg][0], srcB);
            float y1 = __shfl_sync(0xffffffffu, p[kg][1], srcB);
            float y2 = __shfl_sync(0xffffffffu, p[kg][2], srcB);
            float y3 = __shfl_sync(0xffffffffu, p[kg][3], srcB);
            uint32_t pa[4];
            pa[0] = fu(f2tf(oddt ? x1 : x0));
            pa[1] = fu(f2tf(oddt ? x3 : x2));
            pa[2] = fu(f2tf(oddt ? y1 : y0));
            pa[3] = fu(f2tf(oddt ? y3 : y2));
            float2 e0 = Ep[rl0 * QPAD + kg * 4 + qt];
            float2 e1 = Ep[rh0 * QPAD + kg * 4 + qt];
            uint32_t ea[4] = {fu(e0.x), fu(e1.x), fu(e0.y), fu(e1.y)};
            #pragma unroll
            for (int ng = 0; ng < 8; ++ng) {
                float2 b2 = Vp[(kg * 4 + qt) * VPAD + ng * 8 + quad];
                uint32_t bb[2] = {fu(b2.x), fu(b2.y)};
                mma8(os[ng], pa, bb);
                mma8(op[ng], ea, bb);
            }
        }
    }

    // Epilogue: ctx = os / rowsum + op, written as [b, n, h*64 + c]
    const float il = 1.f / rs_lo, ih = 1.f / rs_hi;
    #pragma unroll
    for (int ng = 0; ng < 8; ++ng) {
        const int col = h * 64 + ng * 8 + qt * 2;
        float* d0 = xout + ((size_t)b * 1024 + q0 + rl0) * 1024 + col;
        float* d1 = xout + ((size_t)b * 1024 + q0 + rh0) * 1024 + col;
        *(float2*)d0 = make_float2(os[ng][0] * il + op[ng][0], os[ng][1] * il + op[ng][1]);
        *(float2*)d1 = make_float2(os[ng][2] * ih + op[ng][2], os[ng][3] * ih + op[ng][3]);
    }
}

// ---------------------------------------------------------------------------
// MLP GEMM: out[4096,1024] = act(A @ W + bias). CTA tile 64x128, 128 threads,
// 4 warps of 16x128. Packed-pair smem, tf32 MMA, K chunks of 64.
// ---------------------------------------------------------------------------
__global__ __launch_bounds__(128, 4)
void mlp_gemm(const float* __restrict__ A, const float* __restrict__ W,
              const float* __restrict__ bias, float* __restrict__ out, int act)
{
    extern __shared__ float2 sm2[];
    float2* Ap = sm2;                 // [64][QPAD]
    float2* Wp = Ap + 64 * QPAD;      // [32][WPAD]

    const int r0 = blockIdx.y * 64, o0 = blockIdx.x * 128;
    const int tid = threadIdx.x, lane = tid & 31, warp = tid >> 5;
    const int quad = lane >> 2, qt = lane & 3;
    const int rl0 = warp * 16 + quad, rh0 = rl0 + 8;

    float acc[16][4] = {};
    for (int k0 = 0; k0 < 1024; k0 += 64) {
        __syncthreads();
        #pragma unroll
        for (int t = 0; t < 4; ++t) {
            int task = tid + t * 128;        // 512: r(64) x kg(8)
            int r = task >> 3, kg = task & 7;
            const float* s = A + (size_t)(r0 + r) * 1024 + k0 + kg * 8;
            pack_pairs(&Ap[r * QPAD + kg * 4], *(const float4*)s, *(const float4*)(s + 4));
        }
        #pragma unroll
        for (int t = 0; t < 4; ++t) {
            int task = tid + t * 128;        // 512: pair(32) x colchunk(16)
            int pi = task >> 4, c = (task & 15) * 8;
            int kk = (pi >> 2) * 8 + (pi & 3);
            const float* s0 = W + (size_t)(k0 + kk) * 1024 + o0 + c;
            const float* s1 = s0 + 4 * 1024;
            float4 a0 = *(const float4*)s0, a1 = *(const float4*)(s0 + 4);
            float4 b0 = *(const float4*)s1, b1 = *(const float4*)(s1 + 4);
            float2* d = &Wp[pi * WPAD + c];
            *(float4*)(d)     = make_float4(f2tf(a0.x), f2tf(b0.x), f2tf(a0.y), f2tf(b0.y));
            *(float4*)(d + 2) = make_float4(f2tf(a0.z), f2tf(b0.z), f2tf(a0.w), f2tf(b0.w));
            *(float4*)(d + 4) = make_float4(f2tf(a1.x), f2tf(b1.x), f2tf(a1.y), f2tf(b1.y));
            *(float4*)(d + 6) = make_float4(f2tf(a1.z), f2tf(b1.z), f2tf(a1.w), f2tf(b1.w));
        }
        __syncthreads();
        #pragma unroll
        for (int kg = 0; kg < 8; ++kg) {
            float2 a0 = Ap[rl0 * QPAD + kg * 4 + qt];
            float2 a1 = Ap[rh0 * QPAD + kg * 4 + qt];
            uint32_t a[4] = {fu(a0.x), fu(a1.x), fu(a0.y), fu(a1.y)};
            #pragma unroll
            for (int ng = 0; ng < 16; ++ng) {
                float2 b2 = Wp[(kg * 4 + qt) * WPAD + ng * 8 + quad];
                uint32_t bb[2] = {fu(b2.x), fu(b2.y)};
                mma8(acc[ng], a, bb);
            }
        }
    }

    #pragma unroll
    for (int ng = 0; ng < 16; ++ng) {
        const int col = o0 + ng * 8 + qt * 2;
        const float b0v = bias[col], b1v = bias[col + 1];
        float x0 = acc[ng][0] + b0v, x1 = acc[ng][1] + b1v;
        float x2 = acc[ng][2] + b0v, x3 = acc[ng][3] + b1v;
        if (act) {
            x0 = x0 / (1.f + __expf(-x0)); x1 = x1 / (1.f + __expf(-x1));
            x2 = x2 / (1.f + __expf(-x2)); x3 = x3 / (1.f + __expf(-x3));
        }
        *(float2*)(out + (size_t)(r0 + rl0) * 1024 + col) = make_float2(x0, x1);
        *(float2*)(out + (size_t)(r0 + rh0) * 1024 + col) = make_float2(x2, x3);
    }
}

// ---------------------------------------------------------------------------
extern "C" void kernel_launch(void* const* d_in, const int* in_sizes, int n_in,
                              void* d_out, int out_size)
{
    const float* q  = (const float*)d_in[0];
    const float* k  = (const float*)d_in[1];
    const float* v  = (const float*)d_in[2];
    const float* pe = (const float*)d_in[3];
    const float* w1 = (const float*)d_in[4];
    const float* b1 = (const float*)d_in[5];
    const float* w2 = (const float*)d_in[6];
    const float* b2 = (const float*)d_in[7];
    float* out = (float*)d_out;

    float *xp = nullptr, *hp = nullptr;
    cudaGetSymbolAddress((void**)&xp, g_x);
    cudaGetSymbolAddress((void**)&hp, g_h);

    const int ATTN_SMEM = (3 * 64 * QPAD + 32 * VPAD) * (int)sizeof(float2); // 69120 B
    const int MLP_SMEM  = (64 * QPAD + 32 * WPAD) * (int)sizeof(float2);     // 50688 B
    cudaFuncSetAttribute(attn_kernel, cudaFuncAttributeMaxDynamicSharedMemorySize, ATTN_SMEM);
    cudaFuncSetAttribute(mlp_gemm,    cudaFuncAttributeMaxDynamicSharedMemorySize, MLP_SMEM);

    attn_kernel<<<dim3(4, 16, 16), 128, ATTN_SMEM>>>(q, k, v, pe, xp);
    mlp_gemm<<<dim3(8, 64), 128, MLP_SMEM>>>(xp, w1, b1, hp, 1);
    mlp_gemm<<<dim3(8, 64), 128, MLP_SMEM>>>(hp, w2, b2, out, 0);
}

// round 5
// speedup vs baseline: 2.7085x; 2.7085x over previous
#include <cuda_runtime.h>
#include <cuda_fp16.h>
#include <cstdint>

// Scratch (allocation-free rule: device globals)
__device__ __align__(16) __half g_qh[4194304];
__device__ __align__(16) __half g_kh[4194304];
__device__ __align__(16) __half g_vh[4194304];
__device__ __align__(16) __half g_peh[16777216];
__device__ __align__(16) __half g_xh[4194304];   // attention out (half), [B*N, D]
__device__ __align__(16) __half g_hh[4194304];   // MLP hidden (half), [B*N, D]
__device__ __align__(16) __half g_w1h[1048576];  // W1^T [out][in] half
__device__ __align__(16) __half g_w2h[1048576];  // W2^T [out][in] half

__device__ __forceinline__ uint32_t h2u(float a, float b) {
    __half2 h = __floats2half2_rn(a, b);
    return *reinterpret_cast<uint32_t*>(&h);
}

// D += A @ B : m16n8k16, fp16 in, fp32 accumulate
__device__ __forceinline__ void mma16(float* c, const uint32_t* a, const uint32_t* b) {
    asm volatile("mma.sync.aligned.m16n8k16.row.col.f32.f16.f16.f32 "
        "{%0,%1,%2,%3}, {%4,%5,%6,%7}, {%8,%9}, {%0,%1,%2,%3};"
        : "+f"(c[0]), "+f"(c[1]), "+f"(c[2]), "+f"(c[3])
        : "r"(a[0]), "r"(a[1]), "r"(a[2]), "r"(a[3]), "r"(b[0]), "r"(b[1]));
}

// ---------------------------------------------------------------------------
// Prep kernels (run once per call)
// ---------------------------------------------------------------------------
__global__ void cvt_f2h(const float4* __restrict__ src, uint2* __restrict__ dst, int n4)
{
    int i = blockIdx.x * blockDim.x + threadIdx.x;
    if (i < n4) {
        float4 v = src[i];
        uint2 o;
        o.x = h2u(v.x, v.y);
        o.y = h2u(v.z, v.w);
        dst[i] = o;
    }
}

__global__ void transpose_h(const float* __restrict__ src, __half* __restrict__ dst)
{
    __shared__ float t[32][33];
    int x = blockIdx.x * 32 + threadIdx.x;
    int y = blockIdx.y * 32 + threadIdx.y;
    #pragma unroll
    for (int j = 0; j < 32; j += 8)
        t[threadIdx.y + j][threadIdx.x] = src[(size_t)(y + j) * 1024 + x];
    __syncthreads();
    x = blockIdx.y * 32 + threadIdx.x;
    y = blockIdx.x * 32 + threadIdx.y;
    #pragma unroll
    for (int j = 0; j < 32; j += 8)
        dst[(size_t)(y + j) * 1024 + x] = __float2half_rn(t[threadIdx.x][threadIdx.y + j]);
}

// ---------------------------------------------------------------------------
// Fused attention: ctx = softmax(Q K^T * scale) @ V + pe @ V   (fp16 MMA)
// CTA = (b, h, 64-row q-tile), 128 threads. Fragment-major smem (one LDS.64
// per MMA operand, conflict-free). P: C-frag -> A-frag purely in registers.
// exp without max-subtraction (scores ~N(0,1)); running fp32 row sums.
// ---------------------------------------------------------------------------
__global__ __launch_bounds__(128, 3)
void attn_kernel(const __half* __restrict__ qh, const __half* __restrict__ kh,
                 const __half* __restrict__ vh, const __half* __restrict__ peh,
                 __half* __restrict__ xout)
{
    extern __shared__ uint2 smf[];
    uint2* Kf = smf;             // 32 groups of 33 (pad) : K B-frags
    uint2* Vf = smf + 32 * 33;   // 32 groups : V B-frags
    uint2* Ef = smf + 64 * 33;   // 32 groups : pe A-frags

    const int b = blockIdx.x, h = blockIdx.y, q0 = blockIdx.z * 64;
    const int tid = threadIdx.x, lane = tid & 31, warp = tid >> 5;
    const int quad = lane >> 2, qt = lane & 3;
    const int rl0 = warp * 16 + quad, rh0 = rl0 + 8;

    const __half* qb  = qh  + ((size_t)(b * 16 + h) * 1024 + q0) * 64;
    const __half* kb  = kh  + (size_t)(b * 16 + h) * 65536;
    const __half* vb  = vh  + (size_t)(b * 16 + h) * 65536;
    const __half* peb = peh + ((size_t)h * 1024 + q0) * 1024;

    // Q A-fragments, resident in registers (4 k-groups of 16)
    uint32_t qa[4][4];
    #pragma unroll
    for (int kg = 0; kg < 4; ++kg) {
        qa[kg][0] = *(const uint32_t*)(qb + rl0 * 64 + kg * 16 + 2 * qt);
        qa[kg][1] = *(const uint32_t*)(qb + rh0 * 64 + kg * 16 + 2 * qt);
        qa[kg][2] = *(const uint32_t*)(qb + rl0 * 64 + kg * 16 + 8 + 2 * qt);
        qa[kg][3] = *(const uint32_t*)(qb + rh0 * 64 + kg * 16 + 8 + 2 * qt);
    }

    float os[8][4] = {};   // P @ V (unnormalized)
    float op[8][4] = {};   // pe @ V
    float rs_lo = 0.f, rs_hi = 0.f;
    const float c2 = 0.125f * 1.44269504088896340736f;  // scale * log2(e)

    for (int kt = 0; kt < 16; ++kt) {
        const int k0 = kt * 64;
        __syncthreads();
        // K tile -> B-frag layout: group = ng*4+kg, lane uint2 = (b0,b1)
        #pragma unroll
        for (int t = 0; t < 4; ++t) {
            int task = tid + t * 128;
            int r = task >> 3, c8 = task & 7;
            uint4 u = *(const uint4*)(kb + (size_t)(k0 + r) * 64 + c8 * 8);
            int kg = c8 >> 1, slot = c8 & 1;
            uint32_t* w = (uint32_t*)(Kf + ((r >> 3) * 4 + kg) * 33 + (r & 7) * 4) + slot;
            w[0] = u.x; w[2] = u.y; w[4] = u.z; w[6] = u.w;
        }
        // pe tile -> A-frag layout: group = (m16*2+h)*4+kg
        #pragma unroll
        for (int t = 0; t < 4; ++t) {
            int task = tid + t * 128;
            int r = task >> 3, c8 = task & 7;
            uint4 u = *(const uint4*)(peb + (size_t)r * 1024 + k0 + c8 * 8);
            int kg = c8 >> 1, slot = c8 & 1;
            uint32_t* w = (uint32_t*)(Ef + (((r >> 4) * 2 + ((r >> 3) & 1)) * 4 + kg) * 33
                                      + (r & 7) * 4) + slot;
            w[0] = u.x; w[2] = u.y; w[4] = u.z; w[6] = u.w;
        }
        // V tile -> B-frag layout (pairs along k via PRMT): group = kg*8+ng
        #pragma unroll
        for (int t = 0; t < 2; ++t) {
            int task = tid + t * 128;
            int pr = task >> 3, c8 = task & 7;
            const __half* s0 = vb + (size_t)(k0 + 2 * pr) * 64 + c8 * 8;
            uint4 A4 = *(const uint4*)s0;
            uint4 B4 = *(const uint4*)(s0 + 64);
            int kg = pr >> 3, qv = pr & 3, slot = (pr >> 2) & 1;
            uint32_t* w = (uint32_t*)(Vf + (kg * 8 + c8) * 33) + slot;
            uint32_t av[4] = {A4.x, A4.y, A4.z, A4.w};
            uint32_t bv[4] = {B4.x, B4.y, B4.z, B4.w};
            #pragma unroll
            for (int j = 0; j < 4; ++j) {
                w[((2 * j)     * 4 + qv) * 2] = __byte_perm(av[j], bv[j], 0x5410);
                w[((2 * j + 1) * 4 + qv) * 2] = __byte_perm(av[j], bv[j], 0x7632);
            }
        }
        __syncthreads();

        // ----- S = Q @ K^T (warp strip 16 x 64) -----
        float p[8][4] = {};
        #pragma unroll
        for (int kg = 0; kg < 4; ++kg)
            #pragma unroll
            for (int ng = 0; ng < 8; ++ng) {
                uint2 bb = Kf[(ng * 4 + kg) * 33 + lane];
                mma16(p[ng], qa[kg], (const uint32_t*)&bb);
            }

        // ----- p = exp(S*scale), fp32 row sums -----
        float sl = 0.f, sh = 0.f;
        #pragma unroll
        for (int ng = 0; ng < 8; ++ng) {
            p[ng][0] = exp2f(p[ng][0] * c2); p[ng][1] = exp2f(p[ng][1] * c2);
            p[ng][2] = exp2f(p[ng][2] * c2); p[ng][3] = exp2f(p[ng][3] * c2);
            sl += p[ng][0] + p[ng][1];
            sh += p[ng][2] + p[ng][3];
        }
        sl += __shfl_xor_sync(0xffffffffu, sl, 1);
        sl += __shfl_xor_sync(0xffffffffu, sl, 2);
        sh += __shfl_xor_sync(0xffffffffu, sh, 1);
        sh += __shfl_xor_sync(0xffffffffu, sh, 2);
        rs_lo += sl; rs_hi += sh;

        // ----- os += P @ V ; op += E @ V  (V B-frags shared) -----
        #pragma unroll
        for (int kg = 0; kg < 4; ++kg) {
            uint32_t pa[4];   // C-frag -> A-frag: pure register conversion
            pa[0] = h2u(p[2 * kg][0],     p[2 * kg][1]);
            pa[1] = h2u(p[2 * kg][2],     p[2 * kg][3]);
            pa[2] = h2u(p[2 * kg + 1][0], p[2 * kg + 1][1]);
            pa[3] = h2u(p[2 * kg + 1][2], p[2 * kg + 1][3]);
            uint2 e0 = Ef[((warp * 2 + 0) * 4 + kg) * 33 + lane];
            uint2 e1 = Ef[((warp * 2 + 1) * 4 + kg) * 33 + lane];
            uint32_t ea[4] = {e0.x, e1.x, e0.y, e1.y};
            #pragma unroll
            for (int ng = 0; ng < 8; ++ng) {
                uint2 bb = Vf[(kg * 8 + ng) * 33 + lane];
                mma16(os[ng], pa, (const uint32_t*)&bb);
                mma16(op[ng], ea, (const uint32_t*)&bb);
            }
        }
    }

    // Epilogue: ctx = os / rowsum + op -> half, layout [b, n, h*64 + c]
    const float il = 1.f / rs_lo, ih = 1.f / rs_hi;
    #pragma unroll
    for (int ng = 0; ng < 8; ++ng) {
        const int col = h * 64 + ng * 8 + qt * 2;
        *(uint32_t*)(xout + ((size_t)b * 1024 + q0 + rl0) * 1024 + col) =
            h2u(os[ng][0] * il + op[ng][0], os[ng][1] * il + op[ng][1]);
        *(uint32_t*)(xout + ((size_t)b * 1024 + q0 + rh0) * 1024 + col) =
            h2u(os[ng][2] * ih + op[ng][2], os[ng][3] * ih + op[ng][3]);
    }
}

// ---------------------------------------------------------------------------
// MLP GEMM (fp16 MMA): out[4096,1024] = act(A @ Wt^T + bias)
// CTA tile 128x128, 256 threads (8 warps: 4 along M x 2 along N),
// K-chunks of 64, double-buffered fragment-major smem.
// act=1: SiLU -> half out ; act=0: fp32 out.
// ---------------------------------------------------------------------------
__global__ __launch_bounds__(256, 2)
void mlp_tc(const __half* __restrict__ A, const __half* __restrict__ Wt,
            const float* __restrict__ bias, void* __restrict__ outp, int act)
{
    extern __shared__ uint2 smf[];
    const int tid = threadIdx.x, lane = tid & 31, warp = tid >> 5;
    const int wr = warp & 3, wc = warp >> 2;
    const int quad = lane >> 2, qt = lane & 3;
    const int n0 = blockIdx.x * 128, r0 = blockIdx.y * 128;

    float acc[2][8][4] = {};

    auto load = [&](int buf, int kc) {
        uint2* Af = smf + buf * 4224;      // 64 groups A-frags
        uint2* Wf = Af + 64 * 33;          // 64 groups B-frags
        #pragma unroll
        for (int t = 0; t < 4; ++t) {
            int task = tid + t * 256;
            int r = task >> 3, c8 = task & 7;
            uint4 u = *(const uint4*)(A + (size_t)(r0 + r) * 1024 + kc * 64 + c8 * 8);
            int kg = c8 >> 1, slot = c8 & 1;
            uint32_t* w = (uint32_t*)(Af + (((r >> 4) * 2 + ((r >> 3) & 1)) * 4 + kg) * 33
                                      + (r & 7) * 4) + slot;
            w[0] = u.x; w[2] = u.y; w[4] = u.z; w[6] = u.w;
        }
        #pragma unroll
        for (int t = 0; t < 4; ++t) {
            int task = tid + t * 256;
            int r = task >> 3, c8 = task & 7;
            uint4 u = *(const uint4*)(Wt + (size_t)(n0 + r) * 1024 + kc * 64 + c8 * 8);
            int kg = c8 >> 1, slot = c8 & 1;
            uint32_t* w = (uint32_t*)(Wf + ((r >> 3) * 4 + kg) * 33 + (r & 7) * 4) + slot;
            w[0] = u.x; w[2] = u.y; w[4] = u.z; w[6] = u.w;
        }
    };

    load(0, 0);
    __syncthreads();
    for (int kc = 0; kc < 16; ++kc) {
        const int buf = kc & 1;
        if (kc + 1 < 16) load(buf ^ 1, kc + 1);   // prefetch overlaps MMA below
        uint2* Af = smf + buf * 4224;
        uint2* Wf = Af + 64 * 33;
        #pragma unroll
        for (int kg = 0; kg < 4; ++kg) {
            uint32_t a[2][4];
            #pragma unroll
            for (int t = 0; t < 2; ++t) {
                int m16 = wr * 2 + t;
                uint2 lo = Af[((m16 * 2 + 0) * 4 + kg) * 33 + lane];
                uint2 hi = Af[((m16 * 2 + 1) * 4 + kg) * 33 + lane];
                a[t][0] = lo.x; a[t][1] = hi.x; a[t][2] = lo.y; a[t][3] = hi.y;
            }
            #pragma unroll
            for (int ng = 0; ng < 8; ++ng) {
                uint2 bb = Wf[((wc * 8 + ng) * 4 + kg) * 33 + lane];
                mma16(acc[0][ng], a[0], (const uint32_t*)&bb);
                mma16(acc[1][ng], a[1], (const uint32_t*)&bb);
            }
        }
        __syncthreads();
    }

    #pragma unroll
    for (int t = 0; t < 2; ++t) {
        const int rr = r0 + (wr * 2 + t) * 16 + quad;
        #pragma unroll
        for (int ng = 0; ng < 8; ++ng) {
            const int col = n0 + (wc * 8 + ng) * 8 + 2 * qt;
            float2 bv = *(const float2*)(bias + col);
            float x0 = acc[t][ng][0] + bv.x, x1 = acc[t][ng][1] + bv.y;
            float x2 = acc[t][ng][2] + bv.x, x3 = acc[t][ng][3] + bv.y;
            if (act) {
                x0 = x0 / (1.f + __expf(-x0)); x1 = x1 / (1.f + __expf(-x1));
                x2 = x2 / (1.f + __expf(-x2)); x3 = x3 / (1.f + __expf(-x3));
                __half* o = (__half*)outp;
                *(uint32_t*)(o + (size_t)rr * 1024 + col)       = h2u(x0, x1);
                *(uint32_t*)(o + (size_t)(rr + 8) * 1024 + col) = h2u(x2, x3);
            } else {
                float* o = (float*)outp;
                *(float2*)(o + (size_t)rr * 1024 + col)       = make_float2(x0, x1);
                *(float2*)(o + (size_t)(rr + 8) * 1024 + col) = make_float2(x2, x3);
            }
        }
    }
}

// ---------------------------------------------------------------------------
extern "C" void kernel_launch(void* const* d_in, const int* in_sizes, int n_in,
                              void* d_out, int out_size)
{
    const float* q  = (const float*)d_in[0];
    const float* k  = (const float*)d_in[1];
    const float* v  = (const float*)d_in[2];
    const float* pe = (const float*)d_in[3];
    const float* w1 = (const float*)d_in[4];
    const float* b1 = (const float*)d_in[5];
    const float* w2 = (const float*)d_in[6];
    const float* b2 = (const float*)d_in[7];
    float* out = (float*)d_out;

    __half *qh, *kh, *vh, *peh, *xh, *hh, *w1h, *w2h;
    cudaGetSymbolAddress((void**)&qh,  g_qh);
    cudaGetSymbolAddress((void**)&kh,  g_kh);
    cudaGetSymbolAddress((void**)&vh,  g_vh);
    cudaGetSymbolAddress((void**)&peh, g_peh);
    cudaGetSymbolAddress((void**)&xh,  g_xh);
    cudaGetSymbolAddress((void**)&hh,  g_hh);
    cudaGetSymbolAddress((void**)&w1h, g_w1h);
    cudaGetSymbolAddress((void**)&w2h, g_w2h);

    const int ATTN_SMEM = 96 * 33 * (int)sizeof(uint2);        // 25344 B
    const int MLP_SMEM  = 2 * 4224 * (int)sizeof(uint2);       // 67584 B
    cudaFuncSetAttribute(attn_kernel, cudaFuncAttributeMaxDynamicSharedMemorySize, ATTN_SMEM);
    cudaFuncSetAttribute(mlp_tc,      cudaFuncAttributeMaxDynamicSharedMemorySize, MLP_SMEM);

    // one-time conversions
    cvt_f2h<<<4096, 256>>>((const float4*)q,  (uint2*)qh,  1048576);
    cvt_f2h<<<4096, 256>>>((const float4*)k,  (uint2*)kh,  1048576);
    cvt_f2h<<<4096, 256>>>((const float4*)v,  (uint2*)vh,  1048576);
    cvt_f2h<<<16384, 256>>>((const float4*)pe, (uint2*)peh, 4194304);
    transpose_h<<<dim3(32, 32), dim3(32, 8)>>>(w1, w1h);
    transpose_h<<<dim3(32, 32), dim3(32, 8)>>>(w2, w2h);

    attn_kernel<<<dim3(4, 16, 16), 128, ATTN_SMEM>>>(qh, kh, vh, peh, xh);
    mlp_tc<<<dim3(8, 32), 256, MLP_SMEM>>>(xh, w1h, b1, hh, 1);
    mlp_tc<<<dim3(8, 32), 256, MLP_SMEM>>>(hh, w2h, b2, out, 0);
}

// round 6
// speedup vs baseline: 3.5635x; 1.3156x over previous
#include <cuda_runtime.h>
#include <cuda_fp16.h>
#include <cstdint>

// Scratch (allocation-free rule: device globals)
__device__ __align__(16) __half g_qh[4194304];
__device__ __align__(16) __half g_kh[4194304];
__device__ __align__(16) __half g_vh[4194304];
__device__ __align__(16) __half g_peh[16777216];
__device__ __align__(16) __half g_xh[4194304];   // attention out (half), [B*N, D]
__device__ __align__(16) __half g_hh[4194304];   // MLP hidden (half), [B*N, D]
__device__ __align__(16) __half g_w1h[1048576];  // W1^T [out][in] half
__device__ __align__(16) __half g_w2h[1048576];  // W2^T [out][in] half

__device__ __forceinline__ uint32_t h2u(float a, float b) {
    __half2 h = __floats2half2_rn(a, b);
    return *reinterpret_cast<uint32_t*>(&h);
}
__device__ __forceinline__ float ex2f(float x) {
    float r;
    asm("ex2.approx.ftz.f32 %0, %1;" : "=f"(r) : "f"(x));
    return r;
}
__device__ __forceinline__ uint32_t smem_u32(const void* p) {
    uint32_t a;
    asm("{ .reg .u64 t; cvta.to.shared.u64 t, %1; cvt.u32.u64 %0, t; }" : "=r"(a) : "l"(p));
    return a;
}
__device__ __forceinline__ void cpa16(uint32_t dst, const void* src) {
    asm volatile("cp.async.cg.shared.global [%0], [%1], 16;" :: "r"(dst), "l"(src));
}
#define CP_COMMIT() asm volatile("cp.async.commit_group;" ::: "memory")
#define CP_WAIT(n)  asm volatile("cp.async.wait_group %0;" :: "n"(n) : "memory")

__device__ __forceinline__ void ldsm4(uint32_t* r, uint32_t a) {
    asm volatile("ldmatrix.sync.aligned.m8n8.x4.shared.b16 {%0,%1,%2,%3}, [%4];"
        : "=r"(r[0]), "=r"(r[1]), "=r"(r[2]), "=r"(r[3]) : "r"(a));
}
__device__ __forceinline__ void ldsm4t(uint32_t* r, uint32_t a) {
    asm volatile("ldmatrix.sync.aligned.m8n8.x4.trans.shared.b16 {%0,%1,%2,%3}, [%4];"
        : "=r"(r[0]), "=r"(r[1]), "=r"(r[2]), "=r"(r[3]) : "r"(a));
}

// D += A @ B : m16n8k16, fp16 in, fp32 accumulate
__device__ __forceinline__ void mma16(float* c, const uint32_t* a, const uint32_t* b) {
    asm volatile("mma.sync.aligned.m16n8k16.row.col.f32.f16.f16.f32 "
        "{%0,%1,%2,%3}, {%4,%5,%6,%7}, {%8,%9}, {%0,%1,%2,%3};"
        : "+f"(c[0]), "+f"(c[1]), "+f"(c[2]), "+f"(c[3])
        : "r"(a[0]), "r"(a[1]), "r"(a[2]), "r"(a[3]), "r"(b[0]), "r"(b[1]));
}

// ---------------------------------------------------------------------------
// Prep kernels
// ---------------------------------------------------------------------------
__global__ void cvt_f2h(const float4* __restrict__ src, uint2* __restrict__ dst, int n4)
{
    int i = blockIdx.x * blockDim.x + threadIdx.x;
    if (i < n4) {
        float4 v = src[i];
        uint2 o;
        o.x = h2u(v.x, v.y);
        o.y = h2u(v.z, v.w);
        dst[i] = o;
    }
}

__global__ void transpose_h(const float* __restrict__ src, __half* __restrict__ dst)
{
    __shared__ float t[32][33];
    int x = blockIdx.x * 32 + threadIdx.x;
    int y = blockIdx.y * 32 + threadIdx.y;
    #pragma unroll
    for (int j = 0; j < 32; j += 8)
        t[threadIdx.y + j][threadIdx.x] = src[(size_t)(y + j) * 1024 + x];
    __syncthreads();
    x = blockIdx.y * 32 + threadIdx.x;
    y = blockIdx.x * 32 + threadIdx.y;
    #pragma unroll
    for (int j = 0; j < 32; j += 8)
        dst[(size_t)(y + j) * 1024 + x] = __float2half_rn(t[threadIdx.x][threadIdx.y + j]);
}

// ---------------------------------------------------------------------------
// Fused attention: ctx = softmax(Q K^T * scale) @ V + pe @ V
// CTA = (b, h, 64-row q-tile), 128 threads. Row-major smem tiles loaded via
// cp.async (double-buffered K/V/pe), ldmatrix fragment loads, row sums via
// an extra MMA against an all-ones B fragment.
// ---------------------------------------------------------------------------
#define TB 9216                 // tile bytes: 64 rows * 144B (72 halves, padded)
#define RSB 144                 // row stride bytes

__global__ __launch_bounds__(128, 3)
void attn_kernel(const __half* __restrict__ qh, const __half* __restrict__ kh,
                 const __half* __restrict__ vh, const __half* __restrict__ peh,
                 __half* __restrict__ xout)
{
    extern __shared__ __align__(16) char smem[];
    const uint32_t sb = smem_u32(smem);

    const int b = blockIdx.x, h = blockIdx.y, q0 = blockIdx.z * 64;
    const int tid = threadIdx.x, lane = tid & 31, warp = tid >> 5;
    const int quad = lane >> 2, qt = lane & 3;
    const int rl0 = warp * 16 + quad, rh0 = rl0 + 8;

    const __half* qb  = qh  + ((size_t)(b * 16 + h) * 1024 + q0) * 64;
    const __half* kb  = kh  + (size_t)(b * 16 + h) * 65536;
    const __half* vb  = vh  + (size_t)(b * 16 + h) * 65536;
    const __half* peb = peh + ((size_t)h * 1024 + q0) * 1024;

    // per-thread load decomposition: 4 chunks of 16B per 64x64 tile
    int crow[4], ccol[4];
    #pragma unroll
    for (int i = 0; i < 4; ++i) {
        int c = tid + i * 128;
        crow[i] = c >> 3;
        ccol[i] = (c & 7) * 8;   // halves
    }

    auto issue_tile = [&](int kt, int buf) {
        const int k0 = kt * 64;
        const uint32_t Kb = sb + TB * (1 + buf * 3);
        const uint32_t Vb = Kb + TB;
        const uint32_t Eb = Vb + TB;
        #pragma unroll
        for (int i = 0; i < 4; ++i) {
            uint32_t d = crow[i] * RSB + ccol[i] * 2;
            cpa16(Kb + d, kb + (size_t)(k0 + crow[i]) * 64 + ccol[i]);
            cpa16(Vb + d, vb + (size_t)(k0 + crow[i]) * 64 + ccol[i]);
            cpa16(Eb + d, peb + (size_t)crow[i] * 1024 + k0 + ccol[i]);
        }
    };

    // prologue: Q + tile 0 in one group
    #pragma unroll
    for (int i = 0; i < 4; ++i)
        cpa16(sb + crow[i] * RSB + ccol[i] * 2, qb + (size_t)crow[i] * 64 + ccol[i]);
    issue_tile(0, 0);
    CP_COMMIT();

    // ldmatrix lane offsets (bytes)
    const uint32_t laneA = (lane & 15) * RSB + (lane >> 4) * 16;
    const uint32_t laneK = ((lane & 7) + (lane >> 4) * 8) * RSB + ((lane >> 3) & 1) * 16;
    const uint32_t laneV = ((lane & 7) + ((lane >> 3) & 1) * 8) * RSB + (lane >> 4) * 16;

    uint32_t qa[4][4];
    float os[8][4] = {}, op[8][4] = {}, rsum[4] = {};
    const float c2 = 0.125f * 1.44269504088896340736f;  // scale * log2(e)
    const uint32_t ones[2] = {0x3C003C00u, 0x3C003C00u};

    for (int kt = 0; kt < 16; ++kt) {
        const int buf = kt & 1;
        if (kt < 15) { issue_tile(kt + 1, buf ^ 1); CP_COMMIT(); CP_WAIT(1); }
        else CP_WAIT(0);
        __syncthreads();

        if (kt == 0) {
            #pragma unroll
            for (int kg = 0; kg < 4; ++kg)
                ldsm4(qa[kg], sb + warp * 16 * RSB + kg * 32 + laneA);
        }

        const uint32_t Kb = sb + TB * (1 + buf * 3);
        const uint32_t Vb = Kb + TB;
        const uint32_t Eb = Vb + TB;

        // ----- S = Q @ K^T -----
        float p[8][4] = {};
        #pragma unroll
        for (int kg = 0; kg < 4; ++kg)
            #pragma unroll
            for (int ngp = 0; ngp < 4; ++ngp) {
                uint32_t kf[4];
                ldsm4(kf, Kb + ngp * (16 * RSB) + kg * 32 + laneK);
                mma16(p[2 * ngp], qa[kg], kf);
                mma16(p[2 * ngp + 1], qa[kg], kf + 2);
            }

        // ----- P = exp2(S * c2) -> half A-fragments -----
        uint32_t pa[4][4];
        #pragma unroll
        for (int ng = 0; ng < 8; ++ng) {
            p[ng][0] = ex2f(p[ng][0] * c2); p[ng][1] = ex2f(p[ng][1] * c2);
            p[ng][2] = ex2f(p[ng][2] * c2); p[ng][3] = ex2f(p[ng][3] * c2);
        }
        #pragma unroll
        for (int kg = 0; kg < 4; ++kg) {
            pa[kg][0] = h2u(p[2 * kg][0],     p[2 * kg][1]);
            pa[kg][1] = h2u(p[2 * kg][2],     p[2 * kg][3]);
            pa[kg][2] = h2u(p[2 * kg + 1][0], p[2 * kg + 1][1]);
            pa[kg][3] = h2u(p[2 * kg + 1][2], p[2 * kg + 1][3]);
        }

        // ----- os += P @ V ; op += E @ V ; rsum += P @ 1 -----
        #pragma unroll
        for (int kg = 0; kg < 4; ++kg) {
            uint32_t ea[4];
            ldsm4(ea, Eb + warp * (16 * RSB) + kg * 32 + laneA);
            mma16(rsum, pa[kg], ones);
            #pragma unroll
            for (int ngp = 0; ngp < 4; ++ngp) {
                uint32_t vf[4];
                ldsm4t(vf, Vb + kg * (16 * RSB) + ngp * 32 + laneV);
                mma16(os[2 * ngp],     pa[kg], vf);
                mma16(op[2 * ngp],     ea,     vf);
                mma16(os[2 * ngp + 1], pa[kg], vf + 2);
                mma16(op[2 * ngp + 1], ea,     vf + 2);
            }
        }
        __syncthreads();   // compute done before buf is overwritten
    }

    // Epilogue: ctx = os / rowsum + op -> half, layout [b, n, h*64 + c]
    const float il = 1.f / rsum[0], ih = 1.f / rsum[2];
    #pragma unroll
    for (int ng = 0; ng < 8; ++ng) {
        const int col = h * 64 + ng * 8 + qt * 2;
        *(uint32_t*)(xout + ((size_t)b * 1024 + q0 + rl0) * 1024 + col) =
            h2u(os[ng][0] * il + op[ng][0], os[ng][1] * il + op[ng][1]);
        *(uint32_t*)(xout + ((size_t)b * 1024 + q0 + rh0) * 1024 + col) =
            h2u(os[ng][2] * ih + op[ng][2], os[ng][3] * ih + op[ng][3]);
    }
}

// ---------------------------------------------------------------------------
// MLP GEMM (fp16 MMA + cp.async + ldmatrix): out = act(A @ Wt^T + bias)
// CTA tile 128x128, 256 threads (4 M-warps x 2 N-warps), K-chunks of 64,
// double-buffered row-major smem.
// ---------------------------------------------------------------------------
#define MTB 18432               // 128 rows * 144B

__global__ __launch_bounds__(256, 2)
void mlp_tc(const __half* __restrict__ A, const __half* __restrict__ Wt,
            const float* __restrict__ bias, void* __restrict__ outp, int act)
{
    extern __shared__ __align__(16) char smem[];
    const uint32_t sb = smem_u32(smem);

    const int tid = threadIdx.x, lane = tid & 31, warp = tid >> 5;
    const int wr = warp & 3, wc = warp >> 2;
    const int quad = lane >> 2, qt = lane & 3;
    const int n0 = blockIdx.x * 128, r0 = blockIdx.y * 128;

    int crow[4], ccol[4];
    #pragma unroll
    for (int i = 0; i < 4; ++i) {
        int c = tid + i * 256;
        crow[i] = c >> 3;
        ccol[i] = (c & 7) * 8;
    }

    auto issue = [&](int kc, int buf) {
        const uint32_t Ab = sb + buf * 2 * MTB;
        const uint32_t Wb = Ab + MTB;
        #pragma unroll
        for (int i = 0; i < 4; ++i) {
            uint32_t d = crow[i] * RSB + ccol[i] * 2;
            cpa16(Ab + d, A  + (size_t)(r0 + crow[i]) * 1024 + kc * 64 + ccol[i]);
            cpa16(Wb + d, Wt + (size_t)(n0 + crow[i]) * 1024 + kc * 64 + ccol[i]);
        }
    };

    const uint32_t laneA = (lane & 15) * RSB + (lane >> 4) * 16;
    const uint32_t laneK = ((lane & 7) + (lane >> 4) * 8) * RSB + ((lane >> 3) & 1) * 16;

    float acc[2][8][4] = {};

    issue(0, 0);
    CP_COMMIT();

    for (int kc = 0; kc < 16; ++kc) {
        const int buf = kc & 1;
        if (kc < 15) { issue(kc + 1, buf ^ 1); CP_COMMIT(); CP_WAIT(1); }
        else CP_WAIT(0);
        __syncthreads();

        const uint32_t Ab = sb + buf * 2 * MTB;
        const uint32_t Wb = Ab + MTB;

        #pragma unroll
        for (int kg = 0; kg < 4; ++kg) {
            uint32_t a[2][4];
            ldsm4(a[0], Ab + (wr * 32) * RSB + kg * 32 + laneA);
            ldsm4(a[1], Ab + (wr * 32 + 16) * RSB + kg * 32 + laneA);
            #pragma unroll
            for (int ngp = 0; ngp < 4; ++ngp) {
                uint32_t wf[4];
                ldsm4(wf, Wb + (wc * 64 + ngp * 16) * RSB + kg * 32 + laneK);
                mma16(acc[0][2 * ngp],     a[0], wf);
                mma16(acc[1][2 * ngp],     a[1], wf);
                mma16(acc[0][2 * ngp + 1], a[0], wf + 2);
                mma16(acc[1][2 * ngp + 1], a[1], wf + 2);
            }
        }
        __syncthreads();
    }

    #pragma unroll
    for (int t = 0; t < 2; ++t) {
        const int rr = r0 + (wr * 2 + t) * 16 + quad;
        #pragma unroll
        for (int ng = 0; ng < 8; ++ng) {
            const int col = n0 + (wc * 8 + ng) * 8 + 2 * qt;
            float2 bv = *(const float2*)(bias + col);
            float x0 = acc[t][ng][0] + bv.x, x1 = acc[t][ng][1] + bv.y;
            float x2 = acc[t][ng][2] + bv.x, x3 = acc[t][ng][3] + bv.y;
            if (act) {
                x0 = x0 / (1.f + __expf(-x0)); x1 = x1 / (1.f + __expf(-x1));
                x2 = x2 / (1.f + __expf(-x2)); x3 = x3 / (1.f + __expf(-x3));
                __half* o = (__half*)outp;
                *(uint32_t*)(o + (size_t)rr * 1024 + col)       = h2u(x0, x1);
                *(uint32_t*)(o + (size_t)(rr + 8) * 1024 + col) = h2u(x2, x3);
            } else {
                float* o = (float*)outp;
                *(float2*)(o + (size_t)rr * 1024 + col)       = make_float2(x0, x1);
                *(float2*)(o + (size_t)(rr + 8) * 1024 + col) = make_float2(x2, x3);
            }
        }
    }
}

// ---------------------------------------------------------------------------
extern "C" void kernel_launch(void* const* d_in, const int* in_sizes, int n_in,
                              void* d_out, int out_size)
{
    const float* q  = (const float*)d_in[0];
    const float* k  = (const float*)d_in[1];
    const float* v  = (const float*)d_in[2];
    const float* pe = (const float*)d_in[3];
    const float* w1 = (const float*)d_in[4];
    const float* b1 = (const float*)d_in[5];
    const float* w2 = (const float*)d_in[6];
    const float* b2 = (const float*)d_in[7];
    float* out = (float*)d_out;

    __half *qh, *kh, *vh, *peh, *xh, *hh, *w1h, *w2h;
    cudaGetSymbolAddress((void**)&qh,  g_qh);
    cudaGetSymbolAddress((void**)&kh,  g_kh);
    cudaGetSymbolAddress((void**)&vh,  g_vh);
    cudaGetSymbolAddress((void**)&peh, g_peh);
    cudaGetSymbolAddress((void**)&xh,  g_xh);
    cudaGetSymbolAddress((void**)&hh,  g_hh);
    cudaGetSymbolAddress((void**)&w1h, g_w1h);
    cudaGetSymbolAddress((void**)&w2h, g_w2h);

    const int ATTN_SMEM = 7 * TB;        // Q + 2x(K,V,E) = 64512 B
    const int MLP_SMEM  = 4 * MTB;       // 2x(A,W) = 73728 B
    cudaFuncSetAttribute(attn_kernel, cudaFuncAttributeMaxDynamicSharedMemorySize, ATTN_SMEM);
    cudaFuncSetAttribute(mlp_tc,      cudaFuncAttributeMaxDynamicSharedMemorySize, MLP_SMEM);

    // one-time conversions
    cvt_f2h<<<4096, 256>>>((const float4*)q,  (uint2*)qh,  1048576);
    cvt_f2h<<<4096, 256>>>((const float4*)k,  (uint2*)kh,  1048576);
    cvt_f2h<<<4096, 256>>>((const float4*)v,  (uint2*)vh,  1048576);
    cvt_f2h<<<16384, 256>>>((const float4*)pe, (uint2*)peh, 4194304);
    transpose_h<<<dim3(32, 32), dim3(32, 8)>>>(w1, w1h);
    transpose_h<<<dim3(32, 32), dim3(32, 8)>>>(w2, w2h);

    attn_kernel<<<dim3(4, 16, 16), 128, ATTN_SMEM>>>(qh, kh, vh, peh, xh);
    mlp_tc<<<dim3(8, 32), 256, MLP_SMEM>>>(xh, w1h, b1, hh, 1);
    mlp_tc<<<dim3(8, 32), 256, MLP_SMEM>>>(hh, w2h, b2, out, 0);
}